// round 2
// baseline (speedup 1.0000x reference)
#include <cuda_runtime.h>
#include <cuda_bf16.h>

// Problem constants (fixed by the dataset)
#define NMAX 50000
#define DDIM 128
#define EMAX 800000

// Scratch: static device globals (allocation-free rule)
__device__ float g_xj[NMAX * DDIM];   // lrelu(x0 @ W2^T + b2)
__device__ float g_a1[NMAX];
__device__ float g_a2[NMAX];
__device__ int   g_idx_is_64;         // 1 if edge_index is int64, 0 if int32

// ---------------------------------------------------------------------------
// Kernel 0: detect edge_index dtype. If the buffer is little-endian int64
// with node ids < 2^31, the high word of every element is 0. For int32 data,
// odd words are random node ids; 64 consecutive zeros is impossible.
// ---------------------------------------------------------------------------
__global__ void detect_dtype_kernel(const int* __restrict__ ei32)
{
    if (blockIdx.x == 0 && threadIdx.x == 0) {
        int is64 = 1;
        for (int i = 1; i < 128; i += 2)
            if (ei32[i] != 0) { is64 = 0; break; }
        g_idx_is_64 = is64;
    }
}

// ---------------------------------------------------------------------------
// Kernel 1: fused projections.
// Y1 = lrelu(x0 W1^T + b1), Y2 = lrelu(x0 W2^T + b2) as one GEMM with 256
// combined output columns. Y2 -> g_xj; Y1 reduced vs a1_w -> g_a1; Y2
// reduced vs a2_w -> g_a2.
// Tile: 64 rows x 256 cols per block, 256 threads, 8x8 per-thread tile.
// ---------------------------------------------------------------------------
#define TM 64
#define TK 32

__global__ __launch_bounds__(256, 2)
void gemm_proj_kernel(const float* __restrict__ x0,
                      const float* __restrict__ W1, const float* __restrict__ b1,
                      const float* __restrict__ W2, const float* __restrict__ b2,
                      const float* __restrict__ a1w, const float* __restrict__ a1b,
                      const float* __restrict__ a2w, const float* __restrict__ a2b,
                      int n)
{
    __shared__ float Xs[TM][TK + 1];     // 64 x 33
    __shared__ float Ws[256][TK + 1];    // 256 x 33

    const int t  = threadIdx.x;
    const int tx = t & 31;               // lane: column group
    const int ty = t >> 5;               // warp: row group (8 rows each)
    const int row0 = blockIdx.x * TM;

    float acc[8][8];
#pragma unroll
    for (int i = 0; i < 8; i++)
#pragma unroll
        for (int j = 0; j < 8; j++) acc[i][j] = 0.f;

    for (int k0 = 0; k0 < DDIM; k0 += TK) {
        // X tile: 64x32, coalesced along k
#pragma unroll
        for (int j = 0; j < 8; j++) {
            int li = t + 256 * j;
            int r  = li >> 5;
            int kk = li & 31;
            int gr = row0 + r;
            Xs[r][kk] = (gr < n) ? x0[gr * DDIM + k0 + kk] : 0.f;
        }
        // Combined W tile: 256x32, coalesced
#pragma unroll
        for (int j = 0; j < 32; j++) {
            int li = t + 256 * j;
            int c  = li >> 5;
            int kk = li & 31;
            Ws[c][kk] = (c < DDIM) ? W1[c * DDIM + k0 + kk]
                                   : W2[(c - DDIM) * DDIM + k0 + kk];
        }
        __syncthreads();

#pragma unroll
        for (int kk = 0; kk < TK; kk++) {
            float xf[8], wf[8];
#pragma unroll
            for (int rr = 0; rr < 8; rr++) xf[rr] = Xs[ty * 8 + rr][kk];   // broadcast
#pragma unroll
            for (int cc = 0; cc < 8; cc++) wf[cc] = Ws[tx + 32 * cc][kk];  // conflict-free
#pragma unroll
            for (int rr = 0; rr < 8; rr++)
#pragma unroll
                for (int cc = 0; cc < 8; cc++)
                    acc[rr][cc] += xf[rr] * wf[cc];
        }
        __syncthreads();
    }

    // Epilogue: bias + lrelu; cc 0..3 -> W1 cols (reduce vs a1_w),
    // cc 4..7 -> W2 cols (store to g_xj, reduce vs a2_w).
#pragma unroll
    for (int rr = 0; rr < 8; rr++) {
        int gr = row0 + ty * 8 + rr;
        float s1 = 0.f, s2 = 0.f;
#pragma unroll
        for (int cc = 0; cc < 4; cc++) {
            int c = tx + 32 * cc;
            float y = acc[rr][cc] + b1[c];
            y = (y >= 0.f) ? y : 0.2f * y;
            s1 += y * a1w[c];
        }
#pragma unroll
        for (int cc = 4; cc < 8; cc++) {
            int c = tx + 32 * (cc - 4);
            float y = acc[rr][cc] + b2[c];
            y = (y >= 0.f) ? y : 0.2f * y;
            s2 += y * a2w[c];
            if (gr < n) g_xj[gr * DDIM + c] = y;
        }
        // full-warp reduction: each row's 128 cols spread across 32 lanes
#pragma unroll
        for (int off = 16; off > 0; off >>= 1) {
            s1 += __shfl_xor_sync(0xffffffffu, s1, off);
            s2 += __shfl_xor_sync(0xffffffffu, s2, off);
        }
        if (tx == 0 && gr < n) {
            g_a1[gr] = s1 + a1b[0];
            g_a2[gr] = s2 + a2b[0];
        }
    }
}

// ---------------------------------------------------------------------------
// Kernel 2: residual init, out = x0 (float4 grid-stride copy)
// ---------------------------------------------------------------------------
__global__ void copy_kernel(const float4* __restrict__ src, float4* __restrict__ dst,
                            int n4)
{
    int i = blockIdx.x * blockDim.x + threadIdx.x;
    int stride = gridDim.x * blockDim.x;
    for (; i < n4; i += stride) dst[i] = src[i];
}

// ---------------------------------------------------------------------------
// Kernel 3: edges. One warp per edge. att = sigmoid(a1[src] + a2[dst]);
// out[src] += att * x0_j[dst] via red.global.add.v4.f32.
// Index dtype (int32 vs int64) selected by g_idx_is_64.
// ---------------------------------------------------------------------------
__global__ __launch_bounds__(256)
void edge_kernel(const void* __restrict__ ei_raw, float* __restrict__ out, int E)
{
    int gw   = (blockIdx.x * blockDim.x + threadIdx.x) >> 5;
    int lane = threadIdx.x & 31;
    if (gw >= E) return;

    int src, dst;
    if (g_idx_is_64) {
        const long long* e = (const long long*)ei_raw;
        src = (int)e[gw];
        dst = (int)e[(long long)E + gw];
    } else {
        const int* e = (const int*)ei_raw;
        src = e[gw];
        dst = e[E + gw];
    }

    float a = g_a1[src] + g_a2[dst];
    float att = 1.f / (1.f + __expf(-a));

    const float4* vp = reinterpret_cast<const float4*>(g_xj + (size_t)dst * DDIM);
    float4 v = vp[lane];
    float mx = att * v.x, my = att * v.y, mz = att * v.z, mw = att * v.w;

    float* oaddr = out + (size_t)src * DDIM + lane * 4;
    asm volatile("red.global.add.v4.f32 [%0], {%1, %2, %3, %4};"
                 :: "l"(oaddr), "f"(mx), "f"(my), "f"(mz), "f"(mw)
                 : "memory");
}

// ---------------------------------------------------------------------------
// Launcher
// Inputs (metadata order): x0, x1(unused), edge_index([2,E]),
//   W1, b1, W2, b2, a1_w, a1_b, a2_w, a2_b
// ---------------------------------------------------------------------------
extern "C" void kernel_launch(void* const* d_in, const int* in_sizes, int n_in,
                              void* d_out, int out_size)
{
    const float* x0  = (const float*)d_in[0];
    const void*  ei  = d_in[2];
    const float* W1  = (const float*)d_in[3];
    const float* b1  = (const float*)d_in[4];
    const float* W2  = (const float*)d_in[5];
    const float* b2  = (const float*)d_in[6];
    const float* a1w = (const float*)d_in[7];
    const float* a1b = (const float*)d_in[8];
    const float* a2w = (const float*)d_in[9];
    const float* a2b = (const float*)d_in[10];
    float* out = (float*)d_out;

    const int n = in_sizes[0] / DDIM;         // 50000
    const int E = in_sizes[2] / 2;            // 800000

    // 0) dtype probe (must precede edge kernel; same stream => ordered)
    detect_dtype_kernel<<<1, 1>>>((const int*)ei);

    // 1) projections
    int gblocks = (n + TM - 1) / TM;
    gemm_proj_kernel<<<gblocks, 256>>>(x0, W1, b1, W2, b2, a1w, a1b, a2w, a2b, n);

    // 2) residual init
    int n4 = (n * DDIM) / 4;
    copy_kernel<<<2048, 256>>>((const float4*)x0, (float4*)out, n4);

    // 3) edge scatter
    long long warps = E;
    int eblocks = (int)((warps * 32 + 255) / 256);
    edge_kernel<<<eblocks, 256>>>(ei, out, E);
}

// round 3
// speedup vs baseline: 1.3761x; 1.3761x over previous
#include <cuda_runtime.h>
#include <cuda_bf16.h>

#define NMAX 50000
#define DDIM 128
#define EMAX 800000
#define CAP  64          // adjacency slots per node (Poisson(16) => overflow ~0)
#define OVF_CAP 8192

// Scratch (allocation-free rule: device globals)
__device__ float g_xj[NMAX * DDIM];   // lrelu(x0 @ W2^T + b2)
__device__ float g_a1[NMAX];
__device__ float g_a2[NMAX];
__device__ int   g_idx_is_64;
__device__ int   g_cnt[NMAX];
__device__ int   g_tbl[NMAX * CAP];
__device__ int   g_ovf_cnt;
__device__ long long g_ovf[OVF_CAP];

__device__ __forceinline__ float sigmoidf_fast(float a) {
    return 1.f / (1.f + __expf(-a));
}

// ---------------------------------------------------------------------------
// Kernel 0: detect edge_index dtype (int64 LE => high words all zero).
// ---------------------------------------------------------------------------
__global__ void detect_dtype_kernel(const int* __restrict__ ei32)
{
    if (blockIdx.x == 0 && threadIdx.x == 0) {
        int is64 = 1;
        for (int i = 1; i < 128; i += 2)
            if (ei32[i] != 0) { is64 = 0; break; }
        g_idx_is_64 = is64;
    }
}

// ---------------------------------------------------------------------------
// Kernel 0b: zero counters
// ---------------------------------------------------------------------------
__global__ void zero_kernel(int n)
{
    int i = blockIdx.x * blockDim.x + threadIdx.x;
    if (i < n) g_cnt[i] = 0;
    if (i == 0) g_ovf_cnt = 0;
}

// ---------------------------------------------------------------------------
// Kernel 0c: bucket edges by src (atomic cursor, fixed capacity + overflow)
// ---------------------------------------------------------------------------
__global__ __launch_bounds__(256)
void scatter_build_kernel(const void* __restrict__ ei_raw, int E)
{
    int i = blockIdx.x * blockDim.x + threadIdx.x;
    if (i >= E) return;
    int src, dst;
    if (g_idx_is_64) {
        const long long* e = (const long long*)ei_raw;
        src = (int)e[i];
        dst = (int)e[(long long)E + i];
    } else {
        const int* e = (const int*)ei_raw;
        src = e[i];
        dst = e[E + i];
    }
    int pos = atomicAdd(&g_cnt[src], 1);
    if (pos < CAP) {
        g_tbl[src * CAP + pos] = dst;
    } else {
        int o = atomicAdd(&g_ovf_cnt, 1);
        if (o < OVF_CAP)
            g_ovf[o] = ((long long)src << 32) | (unsigned int)dst;
    }
}

// ---------------------------------------------------------------------------
// Kernel 1: fused projections with packed f32x2 FFMA.
// 256 combined output columns (0..127 -> W1, 128..255 -> W2).
// Per thread: 4 column PAIRS: c0 = 2*tx + 64*p (p=0,1 -> W1; p=2,3 -> W2+128).
// ---------------------------------------------------------------------------
#define TM 64
#define TK 32
#define WPAD 258   // even pad: aligned LDS.64, 2-way conflict on store only

typedef unsigned long long ull;

__global__ __launch_bounds__(256, 2)
void gemm_proj_kernel(const float* __restrict__ x0,
                      const float* __restrict__ W1, const float* __restrict__ b1,
                      const float* __restrict__ W2, const float* __restrict__ b2,
                      const float* __restrict__ a1w, const float* __restrict__ a1b,
                      const float* __restrict__ a2w, const float* __restrict__ a2b,
                      int n)
{
    __shared__ float Xs[TM][TK + 1];      // 64 x 33
    __shared__ float Ws2[TK][WPAD];       // k-major: Ws2[kk][c]

    const int t  = threadIdx.x;
    const int tx = t & 31;
    const int ty = t >> 5;
    const int row0 = blockIdx.x * TM;

    ull acc[8][4];
#pragma unroll
    for (int i = 0; i < 8; i++)
#pragma unroll
        for (int j = 0; j < 4; j++) acc[i][j] = 0ull;

    for (int k0 = 0; k0 < DDIM; k0 += TK) {
        // X tile: 64x32, coalesced along k
#pragma unroll
        for (int j = 0; j < 8; j++) {
            int li = t + 256 * j;
            int r  = li >> 5;
            int kk = li & 31;
            int gr = row0 + r;
            Xs[r][kk] = (gr < n) ? x0[gr * DDIM + k0 + kk] : 0.f;
        }
        // W tile transposed into k-major: Ws2[kk][c] = W[c][k0+kk]
#pragma unroll
        for (int j = 0; j < 32; j++) {
            int li = t + 256 * j;
            int c  = li >> 5;
            int kk = li & 31;
            float w = (c < DDIM) ? W1[c * DDIM + k0 + kk]
                                 : W2[(c - DDIM) * DDIM + k0 + kk];
            Ws2[kk][c] = w;
        }
        __syncthreads();

#pragma unroll
        for (int kk = 0; kk < TK; kk++) {
            // broadcast x, packed {x,x}
            ull xp[8];
#pragma unroll
            for (int rr = 0; rr < 8; rr++) {
                float x = Xs[ty * 8 + rr][kk];
                asm("mov.b64 %0, {%1, %1};" : "=l"(xp[rr]) : "f"(x));
            }
            // column pairs (aligned 8B shared loads)
            ull wp[4];
#pragma unroll
            for (int p = 0; p < 2; p++)
                wp[p] = *reinterpret_cast<const ull*>(&Ws2[kk][2 * tx + 64 * p]);
#pragma unroll
            for (int p = 0; p < 2; p++)
                wp[2 + p] = *reinterpret_cast<const ull*>(&Ws2[kk][128 + 2 * tx + 64 * p]);
#pragma unroll
            for (int rr = 0; rr < 8; rr++)
#pragma unroll
                for (int cp = 0; cp < 4; cp++)
                    asm("fma.rn.f32x2 %0, %1, %2, %0;"
                        : "+l"(acc[rr][cp]) : "l"(xp[rr]), "l"(wp[cp]));
        }
        __syncthreads();
    }

    // Epilogue
    const float a1bv = a1b[0], a2bv = a2b[0];
#pragma unroll
    for (int rr = 0; rr < 8; rr++) {
        int gr = row0 + ty * 8 + rr;
        float s1 = 0.f, s2 = 0.f;
        // W1 pairs
#pragma unroll
        for (int p = 0; p < 2; p++) {
            int c = 2 * tx + 64 * p;
            float lo, hi;
            asm("mov.b64 {%0, %1}, %2;" : "=f"(lo), "=f"(hi) : "l"(acc[rr][p]));
            float y0 = lo + b1[c];
            float y1 = hi + b1[c + 1];
            y0 = (y0 >= 0.f) ? y0 : 0.2f * y0;
            y1 = (y1 >= 0.f) ? y1 : 0.2f * y1;
            s1 += y0 * a1w[c] + y1 * a1w[c + 1];
        }
        // W2 pairs: store to g_xj + reduce
#pragma unroll
        for (int p = 0; p < 2; p++) {
            int c = 2 * tx + 64 * p;
            float lo, hi;
            asm("mov.b64 {%0, %1}, %2;" : "=f"(lo), "=f"(hi) : "l"(acc[rr][2 + p]));
            float y0 = lo + b2[c];
            float y1 = hi + b2[c + 1];
            y0 = (y0 >= 0.f) ? y0 : 0.2f * y0;
            y1 = (y1 >= 0.f) ? y1 : 0.2f * y1;
            s2 += y0 * a2w[c] + y1 * a2w[c + 1];
            if (gr < n)
                *reinterpret_cast<float2*>(&g_xj[gr * DDIM + c]) = make_float2(y0, y1);
        }
#pragma unroll
        for (int off = 16; off > 0; off >>= 1) {
            s1 += __shfl_xor_sync(0xffffffffu, s1, off);
            s2 += __shfl_xor_sync(0xffffffffu, s2, off);
        }
        if (tx == 0 && gr < n) {
            g_a1[gr] = s1 + a1bv;
            g_a2[gr] = s2 + a2bv;
        }
    }
}

// ---------------------------------------------------------------------------
// Kernel 2: gather-side reduction. One warp per src node.
// out[src] = x0[src] + sum_e sigmoid(a1[src]+a2[dst_e]) * g_xj[dst_e]
// ---------------------------------------------------------------------------
__global__ __launch_bounds__(256)
void gather_kernel(const float* __restrict__ x0, float* __restrict__ out, int n)
{
    int gw   = (blockIdx.x * blockDim.x + threadIdx.x) >> 5;
    int lane = threadIdx.x & 31;
    if (gw >= n) return;

    int deg = g_cnt[gw];
    if (deg > CAP) deg = CAP;
    const float a1v = g_a1[gw];
    const int* tbl = g_tbl + gw * CAP;

    float4 acc = make_float4(0.f, 0.f, 0.f, 0.f);

    int e = 0;
    for (; e + 2 <= deg; e += 2) {
        int d0 = tbl[e], d1 = tbl[e + 1];
        float att0 = sigmoidf_fast(a1v + g_a2[d0]);
        float att1 = sigmoidf_fast(a1v + g_a2[d1]);
        float4 v0 = reinterpret_cast<const float4*>(g_xj + (size_t)d0 * DDIM)[lane];
        float4 v1 = reinterpret_cast<const float4*>(g_xj + (size_t)d1 * DDIM)[lane];
        acc.x += att0 * v0.x + att1 * v1.x;
        acc.y += att0 * v0.y + att1 * v1.y;
        acc.z += att0 * v0.z + att1 * v1.z;
        acc.w += att0 * v0.w + att1 * v1.w;
    }
    if (e < deg) {
        int d0 = tbl[e];
        float att0 = sigmoidf_fast(a1v + g_a2[d0]);
        float4 v0 = reinterpret_cast<const float4*>(g_xj + (size_t)d0 * DDIM)[lane];
        acc.x += att0 * v0.x;
        acc.y += att0 * v0.y;
        acc.z += att0 * v0.z;
        acc.w += att0 * v0.w;
    }

    float4 r = reinterpret_cast<const float4*>(x0 + (size_t)gw * DDIM)[lane];
    float4 o = make_float4(r.x + acc.x, r.y + acc.y, r.z + acc.z, r.w + acc.w);
    reinterpret_cast<float4*>(out + (size_t)gw * DDIM)[lane] = o;
}

// ---------------------------------------------------------------------------
// Kernel 3: overflow edges (rare; red-based, runs after gather)
// ---------------------------------------------------------------------------
__global__ void overflow_kernel(float* __restrict__ out)
{
    int nov = g_ovf_cnt;
    if (nov > OVF_CAP) nov = OVF_CAP;
    int warps = (gridDim.x * blockDim.x) >> 5;
    int gw0   = (blockIdx.x * blockDim.x + threadIdx.x) >> 5;
    int lane  = threadIdx.x & 31;
    for (int i = gw0; i < nov; i += warps) {
        long long p = g_ovf[i];
        int src = (int)(p >> 32);
        int dst = (int)(p & 0xffffffffll);
        float att = sigmoidf_fast(g_a1[src] + g_a2[dst]);
        float4 v = reinterpret_cast<const float4*>(g_xj + (size_t)dst * DDIM)[lane];
        float mx = att * v.x, my = att * v.y, mz = att * v.z, mw = att * v.w;
        float* oaddr = out + (size_t)src * DDIM + lane * 4;
        asm volatile("red.global.add.v4.f32 [%0], {%1, %2, %3, %4};"
                     :: "l"(oaddr), "f"(mx), "f"(my), "f"(mz), "f"(mw)
                     : "memory");
    }
}

// ---------------------------------------------------------------------------
// Launcher. Inputs: x0, x1(unused), edge_index([2,E]),
//   W1, b1, W2, b2, a1_w, a1_b, a2_w, a2_b
// ---------------------------------------------------------------------------
extern "C" void kernel_launch(void* const* d_in, const int* in_sizes, int n_in,
                              void* d_out, int out_size)
{
    const float* x0  = (const float*)d_in[0];
    const void*  ei  = d_in[2];
    const float* W1  = (const float*)d_in[3];
    const float* b1  = (const float*)d_in[4];
    const float* W2  = (const float*)d_in[5];
    const float* b2  = (const float*)d_in[6];
    const float* a1w = (const float*)d_in[7];
    const float* a1b = (const float*)d_in[8];
    const float* a2w = (const float*)d_in[9];
    const float* a2b = (const float*)d_in[10];
    float* out = (float*)d_out;

    const int n = in_sizes[0] / DDIM;   // 50000
    const int E = in_sizes[2] / 2;      // 800000

    detect_dtype_kernel<<<1, 1>>>((const int*)ei);
    zero_kernel<<<(n + 255) / 256, 256>>>(n);
    scatter_build_kernel<<<(E + 255) / 256, 256>>>(ei, E);

    int gblocks = (n + TM - 1) / TM;
    gemm_proj_kernel<<<gblocks, 256>>>(x0, W1, b1, W2, b2, a1w, a1b, a2w, a2b, n);

    int gthreads = n * 32;
    gather_kernel<<<(gthreads + 255) / 256, 256>>>(x0, out, n);

    overflow_kernel<<<16, 256>>>(out);
}

// round 5
// speedup vs baseline: 1.8554x; 1.3483x over previous
#include <cuda_runtime.h>
#include <cuda_bf16.h>

#define NMAX 50000
#define DDIM 128
#define EMAX 800000
#define CAP  64
#define OVF_CAP 8192

// ---------------- device-global scratch (allocation-free rule) -------------
__device__ float g_xj[NMAX * DDIM];
__device__ float g_a1[NMAX];
__device__ float g_a2[NMAX];
__device__ int   g_idx_is_64;
__device__ int   g_cnt[NMAX];
__device__ int   g_tbl[NMAX * CAP];
__device__ int   g_ovf_cnt;
__device__ long long g_ovf[OVF_CAP];
// bf16 hi/lo weights, combined [256][128] row-major (rows 0-127 = W1, 128-255 = W2)
__device__ __align__(16) __nv_bfloat16 g_bh[256 * DDIM];
__device__ __align__(16) __nv_bfloat16 g_bl[256 * DDIM];

__device__ __forceinline__ float sigmoidf_fast(float a) {
    return 1.f / (1.f + __expf(-a));
}
__device__ __forceinline__ unsigned pack_bf2(float a, float b) {
    __nv_bfloat162 t = __floats2bfloat162_rn(a, b);
    return *reinterpret_cast<unsigned*>(&t);
}
__device__ __forceinline__ unsigned smem_u32(const void* p) {
    unsigned r;
    asm("{ .reg .u64 t; cvta.to.shared.u64 t, %1; cvt.u32.u64 %0, t; }" : "=r"(r) : "l"(p));
    return r;
}
__device__ __forceinline__ void ldm_x4(unsigned* r, unsigned addr) {
    asm volatile("ldmatrix.sync.aligned.m8n8.x4.shared.b16 {%0,%1,%2,%3}, [%4];"
                 : "=r"(r[0]), "=r"(r[1]), "=r"(r[2]), "=r"(r[3]) : "r"(addr));
}
__device__ __forceinline__ void mma16816(float* d, const unsigned* a, const unsigned* b) {
    asm volatile("mma.sync.aligned.m16n8k16.row.col.f32.bf16.bf16.f32 "
                 "{%0,%1,%2,%3}, {%4,%5,%6,%7}, {%8,%9}, {%0,%1,%2,%3};"
                 : "+f"(d[0]), "+f"(d[1]), "+f"(d[2]), "+f"(d[3])
                 : "r"(a[0]), "r"(a[1]), "r"(a[2]), "r"(a[3]), "r"(b[0]), "r"(b[1]));
}

// ---------------------------------------------------------------------------
// Kernel 0: edge_index dtype probe
// ---------------------------------------------------------------------------
__global__ void detect_dtype_kernel(const int* __restrict__ ei32)
{
    if (blockIdx.x == 0 && threadIdx.x == 0) {
        int is64 = 1;
        for (int i = 1; i < 128; i += 2)
            if (ei32[i] != 0) { is64 = 0; break; }
        g_idx_is_64 = is64;
    }
}

__global__ void zero_kernel(int n)
{
    int i = blockIdx.x * blockDim.x + threadIdx.x;
    if (i < n) g_cnt[i] = 0;
    if (i == 0) g_ovf_cnt = 0;
}

__global__ __launch_bounds__(256)
void scatter_build_kernel(const void* __restrict__ ei_raw, int E)
{
    int i = blockIdx.x * blockDim.x + threadIdx.x;
    if (i >= E) return;
    int src, dst;
    if (g_idx_is_64) {
        const long long* e = (const long long*)ei_raw;
        src = (int)e[i];
        dst = (int)e[(long long)E + i];
    } else {
        const int* e = (const int*)ei_raw;
        src = e[i];
        dst = e[E + i];
    }
    int pos = atomicAdd(&g_cnt[src], 1);
    if (pos < CAP) {
        g_tbl[src * CAP + pos] = dst;
    } else {
        int o = atomicAdd(&g_ovf_cnt, 1);
        if (o < OVF_CAP)
            g_ovf[o] = ((long long)src << 32) | (unsigned int)dst;
    }
}

// ---------------------------------------------------------------------------
// W prep: split into bf16 hi/lo, combined [256][128] row-major
// ---------------------------------------------------------------------------
__global__ void prep_w_kernel(const float* __restrict__ W1, const float* __restrict__ W2)
{
    int i = blockIdx.x * blockDim.x + threadIdx.x;
    if (i >= 256 * DDIM) return;
    int c = i >> 7, k = i & 127;
    float w = (c < DDIM) ? W1[c * DDIM + k] : W2[(c - DDIM) * DDIM + k];
    __nv_bfloat16 h = __float2bfloat16(w);
    g_bh[i] = h;
    g_bl[i] = __float2bfloat16(w - __bfloat162float(h));
}

// ---------------------------------------------------------------------------
// Kernel 1: split-bf16 HMMA GEMM. 128 rows/CTA x 256 combined cols, K=128.
// 8 warps (2 row-groups x 4 col-groups), warp tile 64x64.
// cols 0..127 -> Y1 (a1 reduction only), 128..255 -> Y2 (g_xj + a2).
// K chunked by 32 through smem, padded row stride 40 bf16 (80B, ldmatrix
// conflict-free: offsets mod 128B hit all eight 16B slots).
// ---------------------------------------------------------------------------
#define RSB      80        // smem row stride in BYTES (40 bf16)
#define SB_OFF   0         // B tiles: hi 256*80=20480, lo +20480  (40960)
#define SA_OFF   40960     // A tiles: hi 128*80=10240, lo +10240  (20480)
#define P_OFF    61440     // b1,b2,a1w,a2w: 4*512
#define RED_OFF  63488     // red1, red2: 2*512
#define SMEM_TOT 64512

__global__ __launch_bounds__(256, 1)
void gemm_mma_kernel(const float* __restrict__ x0,
                     const float* __restrict__ b1, const float* __restrict__ b2,
                     const float* __restrict__ a1w, const float* __restrict__ a1b,
                     const float* __restrict__ a2w, const float* __restrict__ a2b,
                     int n)
{
    extern __shared__ __align__(16) char sm[];
    const unsigned sb = smem_u32(sm);
    const int tid  = threadIdx.x;
    const int wid  = tid >> 5;
    const int lane = tid & 31;
    const int wr   = wid & 1;        // warp row group (64 rows)
    const int wc   = wid >> 1;       // warp col group (64 cols)
    const int row0 = blockIdx.x * 128;

    float* s_b1  = (float*)(sm + P_OFF);
    float* s_b2  = (float*)(sm + P_OFF + 512);
    float* s_a1w = (float*)(sm + P_OFF + 1024);
    float* s_a2w = (float*)(sm + P_OFF + 1536);
    float* s_r1  = (float*)(sm + RED_OFF);
    float* s_r2  = (float*)(sm + RED_OFF + 512);

    if (tid < 128) {
        s_b1[tid] = b1[tid]; s_b2[tid] = b2[tid];
        s_a1w[tid] = a1w[tid]; s_a2w[tid] = a2w[tid];
        s_r1[tid] = 0.f; s_r2[tid] = 0.f;
    }

    float acc[4][8][4];
#pragma unroll
    for (int i = 0; i < 4; i++)
#pragma unroll
        for (int j = 0; j < 8; j++)
#pragma unroll
            for (int q = 0; q < 4; q++) acc[i][j][q] = 0.f;

    const float4* x4p = reinterpret_cast<const float4*>(x0);

    for (int kc = 0; kc < 4; kc++) {
        const int k0 = kc * 32;
        __syncthreads();   // protect smem from previous chunk's readers

        // ---- A convert: 128 rows x 32 floats -> bf16 hi/lo ----
#pragma unroll
        for (int j = 0; j < 4; j++) {
            int id  = tid + 256 * j;          // 0..1023
            int row = id >> 3;
            int q   = id & 7;                 // which float4 of 8 in chunk
            int grow = row0 + row;
            float4 v = (grow < n) ? x4p[(size_t)grow * 32 + (k0 >> 2) + q]
                                  : make_float4(0.f, 0.f, 0.f, 0.f);
            __nv_bfloat16 hx = __float2bfloat16(v.x), hy = __float2bfloat16(v.y);
            __nv_bfloat16 hz = __float2bfloat16(v.z), hw = __float2bfloat16(v.w);
            uint2 hv, lv;
            hv.x = pack_bf2(v.x, v.y); hv.y = pack_bf2(v.z, v.w);
            lv.x = pack_bf2(v.x - __bfloat162float(hx), v.y - __bfloat162float(hy));
            lv.y = pack_bf2(v.z - __bfloat162float(hz), v.w - __bfloat162float(hw));
            char* dst = sm + SA_OFF + row * RSB + q * 8;
            *reinterpret_cast<uint2*>(dst)         = hv;
            *reinterpret_cast<uint2*>(dst + 10240) = lv;
        }
        // ---- B copy: 256 rows x 32 bf16, hi+lo ----
#pragma unroll
        for (int j = 0; j < 4; j++) {
            int id  = tid + 256 * j;          // 0..1023
            int row = id >> 2;
            int q   = id & 3;                 // which uint4 of 4 in chunk
            const uint4* sh = reinterpret_cast<const uint4*>(g_bh + row * DDIM + k0) + q;
            const uint4* sl = reinterpret_cast<const uint4*>(g_bl + row * DDIM + k0) + q;
            char* dst = sm + SB_OFF + row * RSB + q * 16;
            *reinterpret_cast<uint4*>(dst)         = *sh;
            *reinterpret_cast<uint4*>(dst + 20480) = *sl;
        }
        __syncthreads();

        // ---- fragments + mma, 2 k-steps of 16 ----
#pragma unroll
        for (int ks = 0; ks < 2; ks++) {
            unsigned ah[4][4], al[4][4], bh[8][2], bl[8][2];
            // A: lanes 0-15 -> rows 0-15 @k, lanes 16-31 -> rows 0-15 @k+8
            unsigned abase = sb + SA_OFF + (wr * 64 + (lane & 15)) * RSB
                           + ks * 32 + (lane >> 4) * 16;
#pragma unroll
            for (int mt = 0; mt < 4; mt++) {
                ldm_x4(ah[mt], abase + mt * 16 * RSB);
                ldm_x4(al[mt], abase + mt * 16 * RSB + 10240);
            }
            // B: quad j=lane>>3: row = +((j>>1)*8), khalf = (j&1)
            unsigned bbase = sb + SB_OFF
                           + (wc * 64 + ((lane >> 4) * 8) + (lane & 7)) * RSB
                           + ks * 32 + (((lane >> 3) & 1) * 16);
#pragma unroll
            for (int np = 0; np < 4; np++) {
                ldm_x4(&bh[2 * np][0], bbase + np * 16 * RSB);
                ldm_x4(&bl[2 * np][0], bbase + np * 16 * RSB + 20480);
            }
#pragma unroll
            for (int mt = 0; mt < 4; mt++)
#pragma unroll
                for (int nt = 0; nt < 8; nt++) {
                    mma16816(acc[mt][nt], ah[mt], bh[nt]);   // hh
                    mma16816(acc[mt][nt], ah[mt], bl[nt]);   // hl
                    mma16816(acc[mt][nt], al[mt], bh[nt]);   // lh
                }
        }
    }
    __syncthreads();

    // ---- epilogue ----
    const int qlane = lane >> 2;     // 0..7
    const int cpair = lane & 3;
    const int isY2  = (wc >= 2);
    const float* sbias = isY2 ? s_b2 : s_b1;
    const float* saw   = isY2 ? s_a2w : s_a1w;

#pragma unroll
    for (int mt = 0; mt < 4; mt++) {
        int lr0 = wr * 64 + mt * 16 + qlane;    // local rows
        int lr1 = lr0 + 8;
        int gr0 = row0 + lr0, gr1 = row0 + lr1;
        float pr0 = 0.f, pr1 = 0.f;
#pragma unroll
        for (int nt = 0; nt < 8; nt++) {
            int cb = wc * 64 + nt * 8 + 2 * cpair;          // combined col
            int c  = isY2 ? (cb - 128) : cb;                // 0..126
            float y00 = acc[mt][nt][0] + sbias[c];
            float y01 = acc[mt][nt][1] + sbias[c + 1];
            float y10 = acc[mt][nt][2] + sbias[c];
            float y11 = acc[mt][nt][3] + sbias[c + 1];
            y00 = (y00 >= 0.f) ? y00 : 0.2f * y00;
            y01 = (y01 >= 0.f) ? y01 : 0.2f * y01;
            y10 = (y10 >= 0.f) ? y10 : 0.2f * y10;
            y11 = (y11 >= 0.f) ? y11 : 0.2f * y11;
            pr0 += y00 * saw[c] + y01 * saw[c + 1];
            pr1 += y10 * saw[c] + y11 * saw[c + 1];
            if (isY2) {
                if (gr0 < n)
                    *reinterpret_cast<float2*>(&g_xj[(size_t)gr0 * DDIM + c]) =
                        make_float2(y00, y01);
                if (gr1 < n)
                    *reinterpret_cast<float2*>(&g_xj[(size_t)gr1 * DDIM + c]) =
                        make_float2(y10, y11);
            }
        }
        // quad reduce (4 lanes share each row)
#pragma unroll
        for (int off = 1; off < 4; off <<= 1) {
            pr0 += __shfl_xor_sync(0xffffffffu, pr0, off);
            pr1 += __shfl_xor_sync(0xffffffffu, pr1, off);
        }
        if (cpair == 0) {
            float* red = isY2 ? s_r2 : s_r1;
            atomicAdd(&red[lr0], pr0);
            atomicAdd(&red[lr1], pr1);
        }
    }
    __syncthreads();

    if (tid < 128) {
        int grow = row0 + tid;
        if (grow < n) {
            g_a1[grow] = s_r1[tid] + a1b[0];
            g_a2[grow] = s_r2[tid] + a2b[0];
        }
    }
}

// ---------------------------------------------------------------------------
// Kernel 2: gather-side reduction (one warp per src node), fused residual
// ---------------------------------------------------------------------------
__global__ __launch_bounds__(256)
void gather_kernel(const float* __restrict__ x0, float* __restrict__ out, int n)
{
    int gw   = (blockIdx.x * blockDim.x + threadIdx.x) >> 5;
    int lane = threadIdx.x & 31;
    if (gw >= n) return;

    int deg = g_cnt[gw];
    if (deg > CAP) deg = CAP;
    const float a1v = g_a1[gw];
    const int* tbl = g_tbl + gw * CAP;

    float4 acc = make_float4(0.f, 0.f, 0.f, 0.f);
    int e = 0;
    for (; e + 2 <= deg; e += 2) {
        int d0 = tbl[e], d1 = tbl[e + 1];
        float att0 = sigmoidf_fast(a1v + g_a2[d0]);
        float att1 = sigmoidf_fast(a1v + g_a2[d1]);
        float4 v0 = reinterpret_cast<const float4*>(g_xj + (size_t)d0 * DDIM)[lane];
        float4 v1 = reinterpret_cast<const float4*>(g_xj + (size_t)d1 * DDIM)[lane];
        acc.x += att0 * v0.x + att1 * v1.x;
        acc.y += att0 * v0.y + att1 * v1.y;
        acc.z += att0 * v0.z + att1 * v1.z;
        acc.w += att0 * v0.w + att1 * v1.w;
    }
    if (e < deg) {
        int d0 = tbl[e];
        float att0 = sigmoidf_fast(a1v + g_a2[d0]);
        float4 v0 = reinterpret_cast<const float4*>(g_xj + (size_t)d0 * DDIM)[lane];
        acc.x += att0 * v0.x; acc.y += att0 * v0.y;
        acc.z += att0 * v0.z; acc.w += att0 * v0.w;
    }

    float4 r = reinterpret_cast<const float4*>(x0 + (size_t)gw * DDIM)[lane];
    reinterpret_cast<float4*>(out + (size_t)gw * DDIM)[lane] =
        make_float4(r.x + acc.x, r.y + acc.y, r.z + acc.z, r.w + acc.w);
}

__global__ void overflow_kernel(float* __restrict__ out)
{
    int nov = g_ovf_cnt;
    if (nov > OVF_CAP) nov = OVF_CAP;
    int warps = (gridDim.x * blockDim.x) >> 5;
    int gw0   = (blockIdx.x * blockDim.x + threadIdx.x) >> 5;
    int lane  = threadIdx.x & 31;
    for (int i = gw0; i < nov; i += warps) {
        long long p = g_ovf[i];
        int src = (int)(p >> 32);
        int dst = (int)(p & 0xffffffffll);
        float att = sigmoidf_fast(g_a1[src] + g_a2[dst]);
        float4 v = reinterpret_cast<const float4*>(g_xj + (size_t)dst * DDIM)[lane];
        float mx = att * v.x, my = att * v.y, mz = att * v.z, mw = att * v.w;
        float* oaddr = out + (size_t)src * DDIM + lane * 4;
        asm volatile("red.global.add.v4.f32 [%0], {%1, %2, %3, %4};"
                     :: "l"(oaddr), "f"(mx), "f"(my), "f"(mz), "f"(mw)
                     : "memory");
    }
}

// ---------------------------------------------------------------------------
// Launcher. Inputs: x0, x1(unused), edge_index([2,E]),
//   W1, b1, W2, b2, a1_w, a1_b, a2_w, a2_b
// ---------------------------------------------------------------------------
extern "C" void kernel_launch(void* const* d_in, const int* in_sizes, int n_in,
                              void* d_out, int out_size)
{
    const float* x0  = (const float*)d_in[0];
    const void*  ei  = d_in[2];
    const float* W1  = (const float*)d_in[3];
    const float* b1  = (const float*)d_in[4];
    const float* W2  = (const float*)d_in[5];
    const float* b2  = (const float*)d_in[6];
    const float* a1w = (const float*)d_in[7];
    const float* a1b = (const float*)d_in[8];
    const float* a2w = (const float*)d_in[9];
    const float* a2b = (const float*)d_in[10];
    float* out = (float*)d_out;

    const int n = in_sizes[0] / DDIM;   // 50000
    const int E = in_sizes[2] / 2;      // 800000

    static int cfg_done = 0;
    if (!cfg_done) {
        cudaFuncSetAttribute(gemm_mma_kernel,
                             cudaFuncAttributeMaxDynamicSharedMemorySize, SMEM_TOT);
        cfg_done = 1;
    }

    detect_dtype_kernel<<<1, 1>>>((const int*)ei);
    zero_kernel<<<(n + 255) / 256, 256>>>(n);
    scatter_build_kernel<<<(E + 255) / 256, 256>>>(ei, E);

    prep_w_kernel<<<(256 * DDIM + 255) / 256, 256>>>(W1, W2);

    int gblocks = (n + 127) / 128;      // 391
    gemm_mma_kernel<<<gblocks, 256, SMEM_TOT>>>(x0, b1, b2, a1w, a1b, a2w, a2b, n);

    int gthreads = n * 32;
    gather_kernel<<<(gthreads + 255) / 256, 256>>>(x0, out, n);

    overflow_kernel<<<16, 256>>>(out);
}

// round 6
// speedup vs baseline: 1.9548x; 1.0536x over previous
#include <cuda_runtime.h>
#include <cuda_bf16.h>

#define NMAX 50000
#define DDIM 128
#define EMAX 800000
#define CAP  64
#define OVF_CAP 8192

// ---------------- device-global scratch (allocation-free rule) -------------
__device__ float g_xj[NMAX * DDIM];
__device__ float g_a1[NMAX];
__device__ float g_a2[NMAX];
__device__ int   g_idx_is_64;
__device__ int   g_cnt[NMAX];
__device__ int   g_tbl[NMAX * CAP];
__device__ int   g_ovf_cnt;
__device__ long long g_ovf[OVF_CAP];
// bf16 hi/lo weights, combined [256][128] row-major (rows 0-127 = W1, 128-255 = W2)
__device__ __align__(16) __nv_bfloat16 g_bh[256 * DDIM];
__device__ __align__(16) __nv_bfloat16 g_bl[256 * DDIM];

__device__ __forceinline__ float sigmoidf_fast(float a) {
    return 1.f / (1.f + __expf(-a));
}
__device__ __forceinline__ unsigned pack_bf2(float a, float b) {
    __nv_bfloat162 t = __floats2bfloat162_rn(a, b);
    return *reinterpret_cast<unsigned*>(&t);
}
__device__ __forceinline__ unsigned smem_u32(const void* p) {
    unsigned r;
    asm("{ .reg .u64 t; cvta.to.shared.u64 t, %1; cvt.u32.u64 %0, t; }" : "=r"(r) : "l"(p));
    return r;
}
__device__ __forceinline__ void ldm_x4(unsigned* r, unsigned addr) {
    asm volatile("ldmatrix.sync.aligned.m8n8.x4.shared.b16 {%0,%1,%2,%3}, [%4];"
                 : "=r"(r[0]), "=r"(r[1]), "=r"(r[2]), "=r"(r[3]) : "r"(addr));
}
__device__ __forceinline__ void mma16816(float* d, const unsigned* a, const unsigned* b) {
    asm volatile("mma.sync.aligned.m16n8k16.row.col.f32.bf16.bf16.f32 "
                 "{%0,%1,%2,%3}, {%4,%5,%6,%7}, {%8,%9}, {%0,%1,%2,%3};"
                 : "+f"(d[0]), "+f"(d[1]), "+f"(d[2]), "+f"(d[3])
                 : "r"(a[0]), "r"(a[1]), "r"(a[2]), "r"(a[3]), "r"(b[0]), "r"(b[1]));
}
__device__ __forceinline__ void cp16(unsigned saddr, const void* gptr) {
    asm volatile("cp.async.cg.shared.global [%0], [%1], 16;"
                 :: "r"(saddr), "l"(gptr) : "memory");
}

// ---------------------------------------------------------------------------
// Fused prep: dtype probe (ballot, parallel loads) + zero counters + W split
// ---------------------------------------------------------------------------
__global__ __launch_bounds__(512)
void fused_prep_kernel(const int* __restrict__ ei32,
                       const float* __restrict__ W1, const float* __restrict__ W2, int n)
{
    int id = blockIdx.x * 512 + threadIdx.x;
    // probe: 64 odd 32-bit words of the first 64 index pairs
    if (blockIdx.x == 0 && threadIdx.x < 32) {
        int lane = threadIdx.x;
        int v = ei32[1 + 2 * lane] | ei32[65 + 2 * lane];
        unsigned m = __ballot_sync(0xffffffffu, v == 0);
        if (lane == 0) g_idx_is_64 = (m == 0xffffffffu) ? 1 : 0;
    }
    if (blockIdx.x == 0 && threadIdx.x == 33) g_ovf_cnt = 0;
    if (id < n) g_cnt[id] = 0;
    if (id < 256 * DDIM) {
        int c = id >> 7, k = id & 127;
        float w = (c < DDIM) ? W1[c * DDIM + k] : W2[(c - DDIM) * DDIM + k];
        __nv_bfloat16 h = __float2bfloat16(w);
        g_bh[id] = h;
        g_bl[id] = __float2bfloat16(w - __bfloat162float(h));
    }
}

__global__ __launch_bounds__(256)
void scatter_build_kernel(const void* __restrict__ ei_raw, int E)
{
    int i = blockIdx.x * blockDim.x + threadIdx.x;
    if (i >= E) return;
    int src, dst;
    if (g_idx_is_64) {
        const long long* e = (const long long*)ei_raw;
        src = (int)e[i];
        dst = (int)e[(long long)E + i];
    } else {
        const int* e = (const int*)ei_raw;
        src = e[i];
        dst = e[E + i];
    }
    int pos = atomicAdd(&g_cnt[src], 1);
    if (pos < CAP) {
        g_tbl[src * CAP + pos] = dst;
    } else {
        int o = atomicAdd(&g_ovf_cnt, 1);
        if (o < OVF_CAP)
            g_ovf[o] = ((long long)src << 32) | (unsigned int)dst;
    }
}

// ---------------------------------------------------------------------------
// GEMM: split-bf16 HMMA, whole-K single stage.
// 512 threads = 16 warps, warp grid 4 (rows) x 4 (cols), warp tile 32x64.
// CTA tile 128 rows x 256 combined cols (0..127 -> Y1/a1, 128..255 -> Y2/a2+g_xj).
// smem rows padded to 272B (17*16B -> ldmatrix conflict-free).
// ---------------------------------------------------------------------------
#define RS       272
#define SA_H     0
#define SA_LD    34816            // 128*272
#define SB_H     69632            // SA_H + 2*34816
#define SB_LD    69632            // 256*272
#define P_OFF    208896           // SB_H + 2*69632
#define RED_OFF  210944
#define SMEM_TOT 211968

__global__ __launch_bounds__(512, 1)
void gemm_mma_kernel(const float* __restrict__ x0,
                     const float* __restrict__ b1, const float* __restrict__ b2,
                     const float* __restrict__ a1w, const float* __restrict__ a1b,
                     const float* __restrict__ a2w, const float* __restrict__ a2b,
                     int n)
{
    extern __shared__ __align__(16) char sm[];
    const unsigned sb = smem_u32(sm);
    const int tid  = threadIdx.x;
    const int wid  = tid >> 5;
    const int lane = tid & 31;
    const int wr   = wid & 3;        // warp row group (32 rows)
    const int wc   = wid >> 2;       // warp col group (64 cols)
    const int row0 = blockIdx.x * 128;

    float* s_b1  = (float*)(sm + P_OFF);
    float* s_b2  = (float*)(sm + P_OFF + 512);
    float* s_a1w = (float*)(sm + P_OFF + 1024);
    float* s_a2w = (float*)(sm + P_OFF + 1536);
    float* s_r1  = (float*)(sm + RED_OFF);
    float* s_r2  = (float*)(sm + RED_OFF + 512);

    if (tid < 128) {
        s_b1[tid] = b1[tid]; s_b2[tid] = b2[tid];
        s_a1w[tid] = a1w[tid]; s_a2w[tid] = a2w[tid];
        s_r1[tid] = 0.f; s_r2[tid] = 0.f;
    }

    // ---- B stage via cp.async: 256 rows x 128 bf16, hi + lo ----
    {
        const char* srch = (const char*)g_bh;
        const char* srcl = (const char*)g_bl;
#pragma unroll
        for (int j = 0; j < 8; j++) {
            int id  = tid + 512 * j;     // 0..4095
            int row = id >> 4;
            int ch  = id & 15;           // 16B chunk within row
            unsigned dst = sb + SB_H + row * RS + ch * 16;
            cp16(dst,         srch + row * 256 + ch * 16);
            cp16(dst + SB_LD, srcl + row * 256 + ch * 16);
        }
    }
    asm volatile("cp.async.commit_group;" ::: "memory");

    // ---- A stage: convert fp32 -> bf16 hi/lo (overlaps with B cp.async) ----
    {
        int row  = tid >> 2;             // 0..127
        int seg  = tid & 3;              // 8 float4 each
        int grow = row0 + row;
        const float4* xr = reinterpret_cast<const float4*>(x0 + (size_t)grow * DDIM);
#pragma unroll
        for (int g = 0; g < 8; g++) {
            int q = seg * 8 + g;         // float4 index within row (0..31)
            float4 v = (grow < n) ? xr[q] : make_float4(0.f, 0.f, 0.f, 0.f);
            __nv_bfloat16 hx = __float2bfloat16(v.x), hy = __float2bfloat16(v.y);
            __nv_bfloat16 hz = __float2bfloat16(v.z), hw = __float2bfloat16(v.w);
            uint2 hv, lv;
            hv.x = pack_bf2(v.x, v.y); hv.y = pack_bf2(v.z, v.w);
            lv.x = pack_bf2(v.x - __bfloat162float(hx), v.y - __bfloat162float(hy));
            lv.y = pack_bf2(v.z - __bfloat162float(hz), v.w - __bfloat162float(hw));
            char* dst = sm + SA_H + row * RS + q * 8;
            *reinterpret_cast<uint2*>(dst)         = hv;
            *reinterpret_cast<uint2*>(dst + SA_LD) = lv;
        }
    }
    asm volatile("cp.async.wait_group 0;" ::: "memory");
    __syncthreads();

    // ---- MMA mainloop: 8 k-steps of 16 ----
    float acc[2][8][4];
#pragma unroll
    for (int i = 0; i < 2; i++)
#pragma unroll
        for (int j = 0; j < 8; j++)
#pragma unroll
            for (int q = 0; q < 4; q++) acc[i][j][q] = 0.f;

#pragma unroll
    for (int ks = 0; ks < 8; ks++) {
        unsigned ah[2][4], al[2][4];
        unsigned abase = sb + SA_H + (wr * 32 + (lane & 15)) * RS
                       + ks * 32 + (lane >> 4) * 16;
#pragma unroll
        for (int mt = 0; mt < 2; mt++) {
            ldm_x4(ah[mt], abase + mt * 16 * RS);
            ldm_x4(al[mt], abase + mt * 16 * RS + SA_LD);
        }
        unsigned bbase = sb + SB_H
                       + (wc * 64 + ((lane >> 4) * 8) + (lane & 7)) * RS
                       + ks * 32 + (((lane >> 3) & 1) * 16);
#pragma unroll
        for (int np = 0; np < 4; np++) {
            unsigned bh[2][2], bl[2][2];
            ldm_x4(&bh[0][0], bbase + np * 16 * RS);
            ldm_x4(&bl[0][0], bbase + np * 16 * RS + SB_LD);
#pragma unroll
            for (int mt = 0; mt < 2; mt++)
#pragma unroll
                for (int j = 0; j < 2; j++) {
                    mma16816(acc[mt][2 * np + j], ah[mt], bh[j]);
                    mma16816(acc[mt][2 * np + j], ah[mt], bl[j]);
                    mma16816(acc[mt][2 * np + j], al[mt], bh[j]);
                }
        }
    }
    __syncthreads();

    // ---- epilogue ----
    const int qlane = lane >> 2;
    const int cpair = lane & 3;
    const int isY2  = (wc >= 2);
    const float* sbias = isY2 ? s_b2 : s_b1;
    const float* saw   = isY2 ? s_a2w : s_a1w;

#pragma unroll
    for (int mt = 0; mt < 2; mt++) {
        int lr0 = wr * 32 + mt * 16 + qlane;
        int lr1 = lr0 + 8;
        int gr0 = row0 + lr0, gr1 = row0 + lr1;
        float pr0 = 0.f, pr1 = 0.f;
#pragma unroll
        for (int nt = 0; nt < 8; nt++) {
            int cb = wc * 64 + nt * 8 + 2 * cpair;
            int c  = isY2 ? (cb - 128) : cb;
            float y00 = acc[mt][nt][0] + sbias[c];
            float y01 = acc[mt][nt][1] + sbias[c + 1];
            float y10 = acc[mt][nt][2] + sbias[c];
            float y11 = acc[mt][nt][3] + sbias[c + 1];
            y00 = (y00 >= 0.f) ? y00 : 0.2f * y00;
            y01 = (y01 >= 0.f) ? y01 : 0.2f * y01;
            y10 = (y10 >= 0.f) ? y10 : 0.2f * y10;
            y11 = (y11 >= 0.f) ? y11 : 0.2f * y11;
            pr0 += y00 * saw[c] + y01 * saw[c + 1];
            pr1 += y10 * saw[c] + y11 * saw[c + 1];
            if (isY2) {
                if (gr0 < n)
                    *reinterpret_cast<float2*>(&g_xj[(size_t)gr0 * DDIM + c]) =
                        make_float2(y00, y01);
                if (gr1 < n)
                    *reinterpret_cast<float2*>(&g_xj[(size_t)gr1 * DDIM + c]) =
                        make_float2(y10, y11);
            }
        }
#pragma unroll
        for (int off = 1; off < 4; off <<= 1) {
            pr0 += __shfl_xor_sync(0xffffffffu, pr0, off);
            pr1 += __shfl_xor_sync(0xffffffffu, pr1, off);
        }
        if (cpair == 0) {
            float* red = isY2 ? s_r2 : s_r1;
            atomicAdd(&red[lr0], pr0);
            atomicAdd(&red[lr1], pr1);
        }
    }
    __syncthreads();

    if (tid < 128) {
        int grow = row0 + tid;
        if (grow < n) {
            g_a1[grow] = s_r1[tid] + a1b[0];
            g_a2[grow] = s_r2[tid] + a2b[0];
        }
    }
}

// ---------------------------------------------------------------------------
// Gather: one warp per src node, 4-edge unroll, fused residual
// ---------------------------------------------------------------------------
__global__ __launch_bounds__(256)
void gather_kernel(const float* __restrict__ x0, float* __restrict__ out, int n)
{
    int gw   = (blockIdx.x * blockDim.x + threadIdx.x) >> 5;
    int lane = threadIdx.x & 31;
    if (gw >= n) return;

    int deg = g_cnt[gw];
    if (deg > CAP) deg = CAP;
    const float a1v = g_a1[gw];
    const int* tbl = g_tbl + gw * CAP;

    float4 acc = make_float4(0.f, 0.f, 0.f, 0.f);
    int e = 0;
    for (; e + 4 <= deg; e += 4) {
        int4 d = *reinterpret_cast<const int4*>(tbl + e);
        float t0 = g_a2[d.x], t1 = g_a2[d.y], t2 = g_a2[d.z], t3 = g_a2[d.w];
        float4 v0 = reinterpret_cast<const float4*>(g_xj + (size_t)d.x * DDIM)[lane];
        float4 v1 = reinterpret_cast<const float4*>(g_xj + (size_t)d.y * DDIM)[lane];
        float4 v2 = reinterpret_cast<const float4*>(g_xj + (size_t)d.z * DDIM)[lane];
        float4 v3 = reinterpret_cast<const float4*>(g_xj + (size_t)d.w * DDIM)[lane];
        float a0 = sigmoidf_fast(a1v + t0);
        float a1f = sigmoidf_fast(a1v + t1);
        float a2f = sigmoidf_fast(a1v + t2);
        float a3 = sigmoidf_fast(a1v + t3);
        acc.x += a0 * v0.x + a1f * v1.x + a2f * v2.x + a3 * v3.x;
        acc.y += a0 * v0.y + a1f * v1.y + a2f * v2.y + a3 * v3.y;
        acc.z += a0 * v0.z + a1f * v1.z + a2f * v2.z + a3 * v3.z;
        acc.w += a0 * v0.w + a1f * v1.w + a2f * v2.w + a3 * v3.w;
    }
    for (; e < deg; e++) {
        int d0 = tbl[e];
        float att0 = sigmoidf_fast(a1v + g_a2[d0]);
        float4 v0 = reinterpret_cast<const float4*>(g_xj + (size_t)d0 * DDIM)[lane];
        acc.x += att0 * v0.x; acc.y += att0 * v0.y;
        acc.z += att0 * v0.z; acc.w += att0 * v0.w;
    }

    float4 r = reinterpret_cast<const float4*>(x0 + (size_t)gw * DDIM)[lane];
    reinterpret_cast<float4*>(out + (size_t)gw * DDIM)[lane] =
        make_float4(r.x + acc.x, r.y + acc.y, r.z + acc.z, r.w + acc.w);
}

__global__ void overflow_kernel(float* __restrict__ out)
{
    int nov = g_ovf_cnt;
    if (nov > OVF_CAP) nov = OVF_CAP;
    int warps = (gridDim.x * blockDim.x) >> 5;
    int gw0   = (blockIdx.x * blockDim.x + threadIdx.x) >> 5;
    int lane  = threadIdx.x & 31;
    for (int i = gw0; i < nov; i += warps) {
        long long p = g_ovf[i];
        int src = (int)(p >> 32);
        int dst = (int)(p & 0xffffffffll);
        float att = sigmoidf_fast(g_a1[src] + g_a2[dst]);
        float4 v = reinterpret_cast<const float4*>(g_xj + (size_t)dst * DDIM)[lane];
        float mx = att * v.x, my = att * v.y, mz = att * v.z, mw = att * v.w;
        float* oaddr = out + (size_t)src * DDIM + lane * 4;
        asm volatile("red.global.add.v4.f32 [%0], {%1, %2, %3, %4};"
                     :: "l"(oaddr), "f"(mx), "f"(my), "f"(mz), "f"(mw)
                     : "memory");
    }
}

// ---------------------------------------------------------------------------
// Launcher. Inputs: x0, x1(unused), edge_index([2,E]),
//   W1, b1, W2, b2, a1_w, a1_b, a2_w, a2_b
// ---------------------------------------------------------------------------
extern "C" void kernel_launch(void* const* d_in, const int* in_sizes, int n_in,
                              void* d_out, int out_size)
{
    const float* x0  = (const float*)d_in[0];
    const void*  ei  = d_in[2];
    const float* W1  = (const float*)d_in[3];
    const float* b1  = (const float*)d_in[4];
    const float* W2  = (const float*)d_in[5];
    const float* b2  = (const float*)d_in[6];
    const float* a1w = (const float*)d_in[7];
    const float* a1b = (const float*)d_in[8];
    const float* a2w = (const float*)d_in[9];
    const float* a2b = (const float*)d_in[10];
    float* out = (float*)d_out;

    const int n = in_sizes[0] / DDIM;   // 50000
    const int E = in_sizes[2] / 2;      // 800000

    static int cfg_done = 0;
    if (!cfg_done) {
        cudaFuncSetAttribute(gemm_mma_kernel,
                             cudaFuncAttributeMaxDynamicSharedMemorySize, SMEM_TOT);
        cfg_done = 1;
    }

    fused_prep_kernel<<<(n + 511) / 512, 512>>>((const int*)ei, W1, W2, n);
    scatter_build_kernel<<<(E + 255) / 256, 256>>>(ei, E);

    int gblocks = (n + 127) / 128;      // 391
    gemm_mma_kernel<<<gblocks, 512, SMEM_TOT>>>(x0, b1, b2, a1w, a1b, a2w, a2b, n);

    int gthreads = n * 32;
    gather_kernel<<<(gthreads + 255) / 256, 256>>>(x0, out, n);

    overflow_kernel<<<8, 256>>>(out);
}

// round 7
// speedup vs baseline: 2.1622x; 1.1061x over previous
#include <cuda_runtime.h>
#include <cuda_bf16.h>

#define NMAX 50000
#define DDIM 128
#define EMAX 800000
#define CAP  64
#define OVF_CAP 8192

// ---------------- device-global scratch (allocation-free rule) -------------
__device__ float g_xj[NMAX * DDIM];
__device__ float g_e1[NMAX];          // exp(-a1)
__device__ float g_e2[NMAX];          // exp(-a2)
__device__ int   g_idx_is_64;
__device__ int   g_cnt[NMAX];
__device__ int   g_tbl[NMAX * CAP];   // zero-init; always holds valid node ids
__device__ int   g_ovf_cnt;
__device__ long long g_ovf[OVF_CAP];
// bf16 hi/lo weights, combined [256][128] row-major (rows 0-127 = W1, 128-255 = W2)
__device__ __align__(16) __nv_bfloat16 g_bh[256 * DDIM];
__device__ __align__(16) __nv_bfloat16 g_bl[256 * DDIM];

__device__ __forceinline__ unsigned pack_bf2(float a, float b) {
    __nv_bfloat162 t = __floats2bfloat162_rn(a, b);
    return *reinterpret_cast<unsigned*>(&t);
}
__device__ __forceinline__ unsigned smem_u32(const void* p) {
    unsigned r;
    asm("{ .reg .u64 t; cvta.to.shared.u64 t, %1; cvt.u32.u64 %0, t; }" : "=r"(r) : "l"(p));
    return r;
}
__device__ __forceinline__ void ldm_x4(unsigned* r, unsigned addr) {
    asm volatile("ldmatrix.sync.aligned.m8n8.x4.shared.b16 {%0,%1,%2,%3}, [%4];"
                 : "=r"(r[0]), "=r"(r[1]), "=r"(r[2]), "=r"(r[3]) : "r"(addr));
}
__device__ __forceinline__ void mma16816(float* d, const unsigned* a, const unsigned* b) {
    asm volatile("mma.sync.aligned.m16n8k16.row.col.f32.bf16.bf16.f32 "
                 "{%0,%1,%2,%3}, {%4,%5,%6,%7}, {%8,%9}, {%0,%1,%2,%3};"
                 : "+f"(d[0]), "+f"(d[1]), "+f"(d[2]), "+f"(d[3])
                 : "r"(a[0]), "r"(a[1]), "r"(a[2]), "r"(a[3]), "r"(b[0]), "r"(b[1]));
}
__device__ __forceinline__ void cp16(unsigned saddr, const void* gptr) {
    asm volatile("cp.async.cg.shared.global [%0], [%1], 16;"
                 :: "r"(saddr), "l"(gptr) : "memory");
}

// ---------------------------------------------------------------------------
// Fused prep: dtype probe + zero counters + W split
// ---------------------------------------------------------------------------
__global__ __launch_bounds__(512)
void fused_prep_kernel(const int* __restrict__ ei32,
                       const float* __restrict__ W1, const float* __restrict__ W2, int n)
{
    int id = blockIdx.x * 512 + threadIdx.x;
    if (blockIdx.x == 0 && threadIdx.x < 32) {
        int lane = threadIdx.x;
        int v = ei32[1 + 2 * lane] | ei32[65 + 2 * lane];
        unsigned m = __ballot_sync(0xffffffffu, v == 0);
        if (lane == 0) g_idx_is_64 = (m == 0xffffffffu) ? 1 : 0;
    }
    if (blockIdx.x == 0 && threadIdx.x == 33) g_ovf_cnt = 0;
    if (id < n) g_cnt[id] = 0;
    if (id < 256 * DDIM) {
        int c = id >> 7, k = id & 127;
        float w = (c < DDIM) ? W1[c * DDIM + k] : W2[(c - DDIM) * DDIM + k];
        __nv_bfloat16 h = __float2bfloat16(w);
        g_bh[id] = h;
        g_bl[id] = __float2bfloat16(w - __bfloat162float(h));
    }
}

__global__ __launch_bounds__(256)
void scatter_build_kernel(const void* __restrict__ ei_raw, int E)
{
    int i = blockIdx.x * blockDim.x + threadIdx.x;
    if (i >= E) return;
    int src, dst;
    if (g_idx_is_64) {
        const long long* e = (const long long*)ei_raw;
        src = (int)e[i];
        dst = (int)e[(long long)E + i];
    } else {
        const int* e = (const int*)ei_raw;
        src = e[i];
        dst = e[E + i];
    }
    int pos = atomicAdd(&g_cnt[src], 1);
    if (pos < CAP) {
        g_tbl[src * CAP + pos] = dst;
    } else {
        int o = atomicAdd(&g_ovf_cnt, 1);
        if (o < OVF_CAP)
            g_ovf[o] = ((long long)src << 32) | (unsigned int)dst;
    }
}

// ---------------------------------------------------------------------------
// GEMM: split-bf16 HMMA, whole-K single stage (unchanged from R6 except
// epilogue stores exp(-a1), exp(-a2)).
// ---------------------------------------------------------------------------
#define RS       272
#define SA_H     0
#define SA_LD    34816
#define SB_H     69632
#define SB_LD    69632
#define P_OFF    208896
#define RED_OFF  210944
#define SMEM_TOT 211968

__global__ __launch_bounds__(512, 1)
void gemm_mma_kernel(const float* __restrict__ x0,
                     const float* __restrict__ b1, const float* __restrict__ b2,
                     const float* __restrict__ a1w, const float* __restrict__ a1b,
                     const float* __restrict__ a2w, const float* __restrict__ a2b,
                     int n)
{
    extern __shared__ __align__(16) char sm[];
    const unsigned sb = smem_u32(sm);
    const int tid  = threadIdx.x;
    const int wid  = tid >> 5;
    const int lane = tid & 31;
    const int wr   = wid & 3;
    const int wc   = wid >> 2;
    const int row0 = blockIdx.x * 128;

    float* s_b1  = (float*)(sm + P_OFF);
    float* s_b2  = (float*)(sm + P_OFF + 512);
    float* s_a1w = (float*)(sm + P_OFF + 1024);
    float* s_a2w = (float*)(sm + P_OFF + 1536);
    float* s_r1  = (float*)(sm + RED_OFF);
    float* s_r2  = (float*)(sm + RED_OFF + 512);

    if (tid < 128) {
        s_b1[tid] = b1[tid]; s_b2[tid] = b2[tid];
        s_a1w[tid] = a1w[tid]; s_a2w[tid] = a2w[tid];
        s_r1[tid] = 0.f; s_r2[tid] = 0.f;
    }

    // B stage via cp.async
    {
        const char* srch = (const char*)g_bh;
        const char* srcl = (const char*)g_bl;
#pragma unroll
        for (int j = 0; j < 8; j++) {
            int id  = tid + 512 * j;
            int row = id >> 4;
            int ch  = id & 15;
            unsigned dst = sb + SB_H + row * RS + ch * 16;
            cp16(dst,         srch + row * 256 + ch * 16);
            cp16(dst + SB_LD, srcl + row * 256 + ch * 16);
        }
    }
    asm volatile("cp.async.commit_group;" ::: "memory");

    // A stage: fp32 -> bf16 hi/lo
    {
        int row  = tid >> 2;
        int seg  = tid & 3;
        int grow = row0 + row;
        const float4* xr = reinterpret_cast<const float4*>(x0 + (size_t)grow * DDIM);
#pragma unroll
        for (int g = 0; g < 8; g++) {
            int q = seg * 8 + g;
            float4 v = (grow < n) ? xr[q] : make_float4(0.f, 0.f, 0.f, 0.f);
            __nv_bfloat16 hx = __float2bfloat16(v.x), hy = __float2bfloat16(v.y);
            __nv_bfloat16 hz = __float2bfloat16(v.z), hw = __float2bfloat16(v.w);
            uint2 hv, lv;
            hv.x = pack_bf2(v.x, v.y); hv.y = pack_bf2(v.z, v.w);
            lv.x = pack_bf2(v.x - __bfloat162float(hx), v.y - __bfloat162float(hy));
            lv.y = pack_bf2(v.z - __bfloat162float(hz), v.w - __bfloat162float(hw));
            char* dst = sm + SA_H + row * RS + q * 8;
            *reinterpret_cast<uint2*>(dst)         = hv;
            *reinterpret_cast<uint2*>(dst + SA_LD) = lv;
        }
    }
    asm volatile("cp.async.wait_group 0;" ::: "memory");
    __syncthreads();

    float acc[2][8][4];
#pragma unroll
    for (int i = 0; i < 2; i++)
#pragma unroll
        for (int j = 0; j < 8; j++)
#pragma unroll
            for (int q = 0; q < 4; q++) acc[i][j][q] = 0.f;

#pragma unroll
    for (int ks = 0; ks < 8; ks++) {
        unsigned ah[2][4], al[2][4];
        unsigned abase = sb + SA_H + (wr * 32 + (lane & 15)) * RS
                       + ks * 32 + (lane >> 4) * 16;
#pragma unroll
        for (int mt = 0; mt < 2; mt++) {
            ldm_x4(ah[mt], abase + mt * 16 * RS);
            ldm_x4(al[mt], abase + mt * 16 * RS + SA_LD);
        }
        unsigned bbase = sb + SB_H
                       + (wc * 64 + ((lane >> 4) * 8) + (lane & 7)) * RS
                       + ks * 32 + (((lane >> 3) & 1) * 16);
#pragma unroll
        for (int np = 0; np < 4; np++) {
            unsigned bh[2][2], bl[2][2];
            ldm_x4(&bh[0][0], bbase + np * 16 * RS);
            ldm_x4(&bl[0][0], bbase + np * 16 * RS + SB_LD);
#pragma unroll
            for (int mt = 0; mt < 2; mt++)
#pragma unroll
                for (int j = 0; j < 2; j++) {
                    mma16816(acc[mt][2 * np + j], ah[mt], bh[j]);
                    mma16816(acc[mt][2 * np + j], ah[mt], bl[j]);
                    mma16816(acc[mt][2 * np + j], al[mt], bh[j]);
                }
        }
    }
    __syncthreads();

    const int qlane = lane >> 2;
    const int cpair = lane & 3;
    const int isY2  = (wc >= 2);
    const float* sbias = isY2 ? s_b2 : s_b1;
    const float* saw   = isY2 ? s_a2w : s_a1w;

#pragma unroll
    for (int mt = 0; mt < 2; mt++) {
        int lr0 = wr * 32 + mt * 16 + qlane;
        int lr1 = lr0 + 8;
        int gr0 = row0 + lr0, gr1 = row0 + lr1;
        float pr0 = 0.f, pr1 = 0.f;
#pragma unroll
        for (int nt = 0; nt < 8; nt++) {
            int cb = wc * 64 + nt * 8 + 2 * cpair;
            int c  = isY2 ? (cb - 128) : cb;
            float y00 = acc[mt][nt][0] + sbias[c];
            float y01 = acc[mt][nt][1] + sbias[c + 1];
            float y10 = acc[mt][nt][2] + sbias[c];
            float y11 = acc[mt][nt][3] + sbias[c + 1];
            y00 = (y00 >= 0.f) ? y00 : 0.2f * y00;
            y01 = (y01 >= 0.f) ? y01 : 0.2f * y01;
            y10 = (y10 >= 0.f) ? y10 : 0.2f * y10;
            y11 = (y11 >= 0.f) ? y11 : 0.2f * y11;
            pr0 += y00 * saw[c] + y01 * saw[c + 1];
            pr1 += y10 * saw[c] + y11 * saw[c + 1];
            if (isY2) {
                if (gr0 < n)
                    *reinterpret_cast<float2*>(&g_xj[(size_t)gr0 * DDIM + c]) =
                        make_float2(y00, y01);
                if (gr1 < n)
                    *reinterpret_cast<float2*>(&g_xj[(size_t)gr1 * DDIM + c]) =
                        make_float2(y10, y11);
            }
        }
#pragma unroll
        for (int off = 1; off < 4; off <<= 1) {
            pr0 += __shfl_xor_sync(0xffffffffu, pr0, off);
            pr1 += __shfl_xor_sync(0xffffffffu, pr1, off);
        }
        if (cpair == 0) {
            float* red = isY2 ? s_r2 : s_r1;
            atomicAdd(&red[lr0], pr0);
            atomicAdd(&red[lr1], pr1);
        }
    }
    __syncthreads();

    if (tid < 128) {
        int grow = row0 + tid;
        if (grow < n) {
            g_e1[grow] = __expf(-(s_r1[tid] + a1b[0]));
            g_e2[grow] = __expf(-(s_r2[tid] + a2b[0]));
        }
    }
}

// ---------------------------------------------------------------------------
// Gather: one warp per src node, chunk-of-8 unconditional loads (att=0 mask).
// att = 1/(1 + e1*e2) == sigmoid(a1+a2).
// ---------------------------------------------------------------------------
__global__ __launch_bounds__(256)
void gather_kernel(const float* __restrict__ x0, float* __restrict__ out, int n)
{
    int gw   = (blockIdx.x * blockDim.x + threadIdx.x) >> 5;
    int lane = threadIdx.x & 31;
    if (gw >= n) return;

    int deg = g_cnt[gw];
    if (deg > CAP) deg = CAP;
    const float e1 = g_e1[gw];
    const int* tbl = g_tbl + gw * CAP;

    float4 acc = make_float4(0.f, 0.f, 0.f, 0.f);

    for (int base = 0; base < deg; base += 8) {
        int4 q0 = *reinterpret_cast<const int4*>(tbl + base);
        int4 q1 = *reinterpret_cast<const int4*>(tbl + base + 4);
        int id[8] = {q0.x, q0.y, q0.z, q0.w, q1.x, q1.y, q1.z, q1.w};
        float att[8];
#pragma unroll
        for (int j = 0; j < 8; j++) att[j] = g_e2[id[j]];
#pragma unroll
        for (int j = 0; j < 8; j++)
            att[j] = (base + j < deg)
                   ? __fdividef(1.f, 1.f + e1 * att[j]) : 0.f;
        float4 v[8];
#pragma unroll
        for (int j = 0; j < 8; j++)
            v[j] = reinterpret_cast<const float4*>(g_xj + (size_t)id[j] * DDIM)[lane];
#pragma unroll
        for (int j = 0; j < 8; j++) {
            acc.x += att[j] * v[j].x;
            acc.y += att[j] * v[j].y;
            acc.z += att[j] * v[j].z;
            acc.w += att[j] * v[j].w;
        }
    }

    float4 r = reinterpret_cast<const float4*>(x0 + (size_t)gw * DDIM)[lane];
    reinterpret_cast<float4*>(out + (size_t)gw * DDIM)[lane] =
        make_float4(r.x + acc.x, r.y + acc.y, r.z + acc.z, r.w + acc.w);
}

__global__ void overflow_kernel(float* __restrict__ out)
{
    int nov = g_ovf_cnt;
    if (nov > OVF_CAP) nov = OVF_CAP;
    int warps = (gridDim.x * blockDim.x) >> 5;
    int gw0   = (blockIdx.x * blockDim.x + threadIdx.x) >> 5;
    int lane  = threadIdx.x & 31;
    for (int i = gw0; i < nov; i += warps) {
        long long p = g_ovf[i];
        int src = (int)(p >> 32);
        int dst = (int)(p & 0xffffffffll);
        float att = __fdividef(1.f, 1.f + g_e1[src] * g_e2[dst]);
        float4 v = reinterpret_cast<const float4*>(g_xj + (size_t)dst * DDIM)[lane];
        float mx = att * v.x, my = att * v.y, mz = att * v.z, mw = att * v.w;
        float* oaddr = out + (size_t)src * DDIM + lane * 4;
        asm volatile("red.global.add.v4.f32 [%0], {%1, %2, %3, %4};"
                     :: "l"(oaddr), "f"(mx), "f"(my), "f"(mz), "f"(mw)
                     : "memory");
    }
}

// ---------------------------------------------------------------------------
// Launcher
// ---------------------------------------------------------------------------
extern "C" void kernel_launch(void* const* d_in, const int* in_sizes, int n_in,
                              void* d_out, int out_size)
{
    const float* x0  = (const float*)d_in[0];
    const void*  ei  = d_in[2];
    const float* W1  = (const float*)d_in[3];
    const float* b1  = (const float*)d_in[4];
    const float* W2  = (const float*)d_in[5];
    const float* b2  = (const float*)d_in[6];
    const float* a1w = (const float*)d_in[7];
    const float* a1b = (const float*)d_in[8];
    const float* a2w = (const float*)d_in[9];
    const float* a2b = (const float*)d_in[10];
    float* out = (float*)d_out;

    const int n = in_sizes[0] / DDIM;   // 50000
    const int E = in_sizes[2] / 2;      // 800000

    static int cfg_done = 0;
    if (!cfg_done) {
        cudaFuncSetAttribute(gemm_mma_kernel,
                             cudaFuncAttributeMaxDynamicSharedMemorySize, SMEM_TOT);
        cfg_done = 1;
    }

    fused_prep_kernel<<<(n + 511) / 512, 512>>>((const int*)ei, W1, W2, n);
    scatter_build_kernel<<<(E + 255) / 256, 256>>>(ei, E);

    int gblocks = (n + 127) / 128;
    gemm_mma_kernel<<<gblocks, 512, SMEM_TOT>>>(x0, b1, b2, a1w, a1b, a2w, a2b, n);

    int gthreads = n * 32;
    gather_kernel<<<(gthreads + 255) / 256, 256>>>(x0, out, n);

    overflow_kernel<<<8, 256>>>(out);
}